// round 7
// baseline (speedup 1.0000x reference)
#include <cuda_runtime.h>
#include <cuda_fp16.h>
#include <mma.h>
#include <cstdint>

using namespace nvcuda;

#define N_NODES 100000
#define N_EDGES 1000000
#define D 64
#define NEG_SLOPE 0.01f

#define LDA 72   // half leading dim for A/B tiles
#define LDC 68   // float leading dim for C tile
#define NBINS 64

// ---------------- scratch (no allocations allowed) ----------------
__device__ int   g_degOi[N_NODES];
__device__ int   g_degIi[N_NODES];
__device__ float g_oisq [N_NODES];
__device__ float g_iisq [N_NODES];
__device__ int2  g_rows [N_NODES];        // {row start, in-degree}
__device__ int   g_cursor[N_NODES];       // fill cursors
__device__ int   g_total;                 // global row-offset cursor
__device__ int   g_esrc[N_EDGES];         // CSR column (src) array
__device__ int   g_rank[N_NODES];         // intra-bin rank
__device__ int   g_binCnt[NBINS];         // degree-bin counters (zero at entry)
__device__ int   g_binOff[NBINS];         // bin offsets
__device__ int   g_perm[N_NODES];         // degree-sorted node order
__device__ __align__(16) half2 g_xh [(size_t)N_NODES * 32];  // x * oisq (128B rows)
__device__ __align__(16) half2 g_h1h[(size_t)N_NODES * 32];  // h1 * oisq
__device__ __align__(16) half  g_W1h[D * D];
__device__ __align__(16) half  g_W2h[D * D];

// ---------------- degree histogram (4 edges/thread) ----------------
__global__ void k_deg(const int* __restrict__ src, const int* __restrict__ dst) {
    int t = blockIdx.x * blockDim.x + threadIdx.x;
    int e0 = t * 4;
    if (e0 + 4 <= N_EDGES) {
        int4 s = *(const int4*)(src + e0);
        int4 d = *(const int4*)(dst + e0);
        atomicAdd(&g_degOi[s.x], 1); atomicAdd(&g_degOi[s.y], 1);
        atomicAdd(&g_degOi[s.z], 1); atomicAdd(&g_degOi[s.w], 1);
        atomicAdd(&g_degIi[d.x], 1); atomicAdd(&g_degIi[d.y], 1);
        atomicAdd(&g_degIi[d.z], 1); atomicAdd(&g_degIi[d.w], 1);
    } else {
        for (int e = e0; e < N_EDGES; e++) {
            atomicAdd(&g_degOi[src[e]], 1);
            atomicAdd(&g_degIi[dst[e]], 1);
        }
    }
}

// ------- row allocation + norms + degree-bin rank; zero counters for replay --
__global__ void k_alloc() {
    int i = blockIdx.x * blockDim.x + threadIdx.x;
    if (i >= N_NODES) return;
    int di = g_degIi[i];
    int dO = g_degOi[i];
    int row = atomicAdd(&g_total, di);     // grouping only; order irrelevant
    g_rows[i] = make_int2(row, di);
    g_cursor[i] = row;
    g_oisq[i] = rsqrtf((float)max(dO, 1));
    g_iisq[i] = rsqrtf((float)max(di, 1));
    int bin = min(di, NBINS - 1);
    g_rank[i] = atomicAdd(&g_binCnt[bin], 1);
    g_degOi[i] = 0;                        // reset for next replay
    g_degIi[i] = 0;
}

// ---------------- 64-bin exclusive scan (1 warp); reset binCnt --------------
__global__ void k_binscan() {
    int t = threadIdx.x;                   // 64 threads
    int v = g_binCnt[t];
    int x = v;
#pragma unroll
    for (int off = 1; off < 32; off <<= 1) {
        int y = __shfl_up_sync(0xFFFFFFFF, x, off);
        if ((t & 31) >= off) x += y;
    }
    __shared__ int w0sum;
    if (t == 31) w0sum = x;
    __syncthreads();
    int excl = x - v + ((t >= 32) ? w0sum : 0);
    g_binOff[t] = excl;
    g_binCnt[t] = 0;                       // reset for next replay
}

// -- convert x -> fp16 (pre-scaled); W1/W2 -> fp16; perm scatter; reset total --
__global__ void k_convert(const float* __restrict__ x,
                          const float* __restrict__ W1,
                          const float* __restrict__ W2) {
    int t = blockIdx.x * blockDim.x + threadIdx.x;
    if (t == 0) g_total = 0;
    if (t < D * D)          g_W1h[t] = __float2half(W1[t]);
    else if (t < 2 * D * D) g_W2h[t - D * D] = __float2half(W2[t - D * D]);
    if (t < N_NODES) {
        int bin = min(g_rows[t].y, NBINS - 1);
        g_perm[g_binOff[bin] + g_rank[t]] = t;
    }
    if (t >= N_NODES * (D / 4)) return;
    int node = t >> 4;                     // 16 float4 per row
    float sc = g_oisq[node];
    float4 v = __ldg((const float4*)x + t);
    g_xh[t * 2 + 0] = __floats2half2_rn(v.x * sc, v.y * sc);
    g_xh[t * 2 + 1] = __floats2half2_rn(v.z * sc, v.w * sc);
}

// ---------------- CSR fill (4 edges/thread) ----------------
__global__ void k_fill(const int* __restrict__ src, const int* __restrict__ dst) {
    int t = blockIdx.x * blockDim.x + threadIdx.x;
    int e0 = t * 4;
    if (e0 + 4 <= N_EDGES) {
        int4 s = *(const int4*)(src + e0);
        int4 d = *(const int4*)(dst + e0);
        int p0 = atomicAdd(&g_cursor[d.x], 1);
        int p1 = atomicAdd(&g_cursor[d.y], 1);
        int p2 = atomicAdd(&g_cursor[d.z], 1);
        int p3 = atomicAdd(&g_cursor[d.w], 1);
        g_esrc[p0] = s.x; g_esrc[p1] = s.y;
        g_esrc[p2] = s.z; g_esrc[p3] = s.w;
    } else {
        for (int e = e0; e < N_EDGES; e++)
            g_esrc[atomicAdd(&g_cursor[dst[e]], 1)] = src[e];
    }
}

// =====================================================================
// Fused layers: degree-sorted nodes, fp16 gather (4 lanes/node,
// 8 nodes/warp, unroll x2) -> half smem -> wmma HMMA -> epilogue
// =====================================================================

#define ACC_U4(V, A)                                                \
    do {                                                            \
        const half2* hv = (const half2*)&(V);                       \
        float2 f0 = __half22float2(hv[0]);                          \
        float2 f1 = __half22float2(hv[1]);                          \
        float2 f2 = __half22float2(hv[2]);                          \
        float2 f3 = __half22float2(hv[3]);                          \
        (A)[0].x += f0.x; (A)[0].y += f0.y;                         \
        (A)[1].x += f1.x; (A)[1].y += f1.y;                         \
        (A)[2].x += f2.x; (A)[2].y += f2.y;                         \
        (A)[3].x += f3.x; (A)[3].y += f3.y;                         \
    } while (0)

__device__ __forceinline__ void group_aggregate(const uint4* __restrict__ feat,
                                                int node, int l,
                                                float2 accA[4], float2 accB[4]) {
    int2 rd = g_rows[node];
    int start = rd.x, deg = rd.y;
    int i = 0;
    int s0 = 0, s1 = 0;
    if (deg >= 2) { s0 = __ldg(&g_esrc[start]); s1 = __ldg(&g_esrc[start + 1]); }
    for (; i + 2 <= deg; ) {
        int t0 = s0, t1 = s1;
        i += 2;
        if (i + 2 <= deg) {
            s0 = __ldg(&g_esrc[start + i]);
            s1 = __ldg(&g_esrc[start + i + 1]);
        }
        uint4 va0 = __ldg(feat + (size_t)t0 * 8 + l);
        uint4 vb0 = __ldg(feat + (size_t)t0 * 8 + 4 + l);
        uint4 va1 = __ldg(feat + (size_t)t1 * 8 + l);
        uint4 vb1 = __ldg(feat + (size_t)t1 * 8 + 4 + l);
        ACC_U4(va0, accA); ACC_U4(vb0, accB);
        ACC_U4(va1, accA); ACC_U4(vb1, accB);
    }
    if (i < deg) {
        int t0 = __ldg(&g_esrc[start + i]);
        uint4 va0 = __ldg(feat + (size_t)t0 * 8 + l);
        uint4 vb0 = __ldg(feat + (size_t)t0 * 8 + 4 + l);
        ACC_U4(va0, accA); ACC_U4(vb0, accB);
    }
}

// aggregate block's 64 (perm) nodes -> half tile sA[64][LDA] (scaled by iisq)
__device__ __forceinline__ void aggregate_phase(const uint4* __restrict__ feat,
                                                int node, int tid, half* sA) {
    int g = tid >> 2, l = tid & 3;
    float2 accA[4] = {{0,0},{0,0},{0,0},{0,0}};
    float2 accB[4] = {{0,0},{0,0},{0,0},{0,0}};
    if (node >= 0) {
        group_aggregate(feat, node, l, accA, accB);
        float fi = g_iisq[node];
#pragma unroll
        for (int j = 0; j < 4; j++) {
            accA[j].x *= fi; accA[j].y *= fi;
            accB[j].x *= fi; accB[j].y *= fi;
        }
    }
    half2 hA[4], hB[4];
#pragma unroll
    for (int j = 0; j < 4; j++) {
        hA[j] = __floats2half2_rn(accA[j].x, accA[j].y);
        hB[j] = __floats2half2_rn(accB[j].x, accB[j].y);
    }
    *(uint4*)&sA[g * LDA + 8 * l]      = *(uint4*)hA;
    *(uint4*)&sA[g * LDA + 32 + 8 * l] = *(uint4*)hB;
}

__device__ __forceinline__ void wmma_gemm(const half* sA, const half* sB,
                                          float* sC, int tid) {
    int w = tid >> 5;
    int mi = w >> 1;
    int ni0 = (w & 1) * 2;
#pragma unroll
    for (int nt = 0; nt < 2; nt++) {
        int ni = ni0 + nt;
        wmma::fragment<wmma::accumulator, 16, 16, 16, float> c;
        wmma::fill_fragment(c, 0.f);
#pragma unroll
        for (int kk = 0; kk < 4; kk++) {
            wmma::fragment<wmma::matrix_a, 16, 16, 16, half, wmma::row_major> a;
            wmma::fragment<wmma::matrix_b, 16, 16, 16, half, wmma::row_major> bf;
            wmma::load_matrix_sync(a, sA + mi * 16 * LDA + kk * 16, LDA);
            wmma::load_matrix_sync(bf, sB + kk * 16 * LDA + ni * 16, LDA);
            wmma::mma_sync(c, a, bf, c);
        }
        wmma::store_matrix_sync(sC + mi * 16 * LDC + ni * 16, c, LDC,
                                wmma::mem_row_major);
    }
}

// Layer 1
__global__ void __launch_bounds__(256) k_layer1(const float* __restrict__ b) {
    __shared__ __align__(16) half  sA[64 * LDA];
    __shared__ __align__(16) half  sB[64 * LDA];
    __shared__ __align__(16) float sC[64 * LDC];
    __shared__ float sBias[D];
    int tid = threadIdx.x;
    int base = blockIdx.x * 64;

    for (int i = tid; i < D * D; i += 256)
        sB[(i >> 6) * LDA + (i & 63)] = g_W1h[i];
    if (tid < D) sBias[tid] = b[tid];

    int slot = base + (tid >> 2);
    int node = (slot < N_NODES) ? g_perm[slot] : -1;
    aggregate_phase((const uint4*)g_xh, node, tid, sA);
    __syncthreads();

    wmma_gemm(sA, sB, sC, tid);
    __syncthreads();

    // epilogue: bias + lrelu + *oisq -> fp16 global (scatter via perm)
    int g = tid >> 2, q = tid & 3;
    int oslot = base + g;
    if (oslot < N_NODES) {
        int on = g_perm[oslot];
        float sc = __ldg(&g_oisq[on]);
        half2 hv[8];
#pragma unroll
        for (int j = 0; j < 8; j++) {
            int c0 = q * 16 + 2 * j;
            float y0 = sC[g * LDC + c0]     + sBias[c0];
            float y1 = sC[g * LDC + c0 + 1] + sBias[c0 + 1];
            y0 = (y0 > 0.f) ? y0 : NEG_SLOPE * y0;
            y1 = (y1 > 0.f) ? y1 : NEG_SLOPE * y1;
            hv[j] = __floats2half2_rn(y0 * sc, y1 * sc);
        }
        uint4* dstp = (uint4*)&g_h1h[(size_t)on * 32];
        dstp[q * 2 + 0] = ((uint4*)hv)[0];
        dstp[q * 2 + 1] = ((uint4*)hv)[1];
    }
}

// Layer 2 + classifier
__global__ void __launch_bounds__(256) k_layer2(
    const float* __restrict__ b2,
    const float* __restrict__ Wc, const float* __restrict__ bc,
    float* __restrict__ out)
{
    __shared__ __align__(16) half  sA[64 * LDA];
    __shared__ __align__(16) half  sB[64 * LDA];
    __shared__ __align__(16) float sC[64 * LDC];
    __shared__ float sBias[D];
    __shared__ float sWc[D * 2];
    int tid = threadIdx.x;
    int base = blockIdx.x * 64;

    for (int i = tid; i < D * D; i += 256)
        sB[(i >> 6) * LDA + (i & 63)] = g_W2h[i];
    if (tid < D) sBias[tid] = b2[tid];
    if (tid >= 64 && tid < 64 + D * 2) sWc[tid - 64] = Wc[tid - 64];

    int slot = base + (tid >> 2);
    int node = (slot < N_NODES) ? g_perm[slot] : -1;
    aggregate_phase((const uint4*)g_h1h, node, tid, sA);
    __syncthreads();

    wmma_gemm(sA, sB, sC, tid);
    __syncthreads();

    // epilogue: bias + lrelu, in-place in sC (same thread reads/writes)
    int g = tid >> 2, q = tid & 3;
#pragma unroll
    for (int j = 0; j < 16; j++) {
        int c0 = q * 16 + j;
        float y = sC[g * LDC + c0] + sBias[c0];
        y = (y > 0.f) ? y : NEG_SLOPE * y;
        sC[g * LDC + c0] = y;
    }
    __syncthreads();

    // classifier: out[n][c] = bc[c] + sum_k h2[n][k] * Wc[k][c]
    if (tid < 128) {
        int n = tid >> 1, c = tid & 1;
        int oslot = base + n;
        if (oslot < N_NODES) {
            int on = g_perm[oslot];
            float s = bc[c];
#pragma unroll
            for (int k = 0; k < D; k++) s += sC[n * LDC + k] * sWc[k * 2 + c];
            out[(size_t)on * 2 + c] = s;
        }
    }
}

// ---------------- launch ----------------
extern "C" void kernel_launch(void* const* d_in, const int* in_sizes, int n_in,
                              void* d_out, int out_size) {
    const float* x   = (const float*)d_in[0];
    const int*   src = (const int*)  d_in[1];
    const int*   dst = (const int*)  d_in[2];
    const float* W1  = (const float*)d_in[3];
    const float* b1  = (const float*)d_in[4];
    const float* W2  = (const float*)d_in[5];
    const float* b2  = (const float*)d_in[6];
    const float* Wc  = (const float*)d_in[7];
    const float* bc  = (const float*)d_in[8];
    float* out = (float*)d_out;

    const int edgeThreads = (N_EDGES + 3) / 4;
    k_deg    <<<(edgeThreads + 255) / 256, 256>>>(src, dst);
    k_alloc  <<<(N_NODES + 255) / 256, 256>>>();
    k_binscan<<<1, NBINS>>>();
    k_convert<<<(N_NODES * (D / 4) + 255) / 256, 256>>>(x, W1, W2);
    k_fill   <<<(edgeThreads + 255) / 256, 256>>>(src, dst);

    k_layer1<<<(N_NODES + 63) / 64, 256>>>(b1);
    k_layer2<<<(N_NODES + 63) / 64, 256>>>(b2, Wc, bc, out);
}

// round 10
// speedup vs baseline: 1.1807x; 1.1807x over previous
#include <cuda_runtime.h>
#include <cuda_fp16.h>
#include <mma.h>
#include <cstdint>

using namespace nvcuda;

#define N_NODES 100000
#define N_EDGES 1000000
#define D 64
#define NEG_SLOPE 0.01f

#define LDA 72   // half leading dim for A/B tiles
#define LDC 68   // float leading dim for C tile

// ---------------- scratch (no allocations allowed) ----------------
__device__ int   g_degOi[N_NODES];
__device__ int   g_degIi[N_NODES];
__device__ float g_oisq [N_NODES];
__device__ float g_iisq [N_NODES];
__device__ int2  g_rows [N_NODES];        // {row start, in-degree}
__device__ int   g_cursor[N_NODES];       // fill cursors
__device__ int   g_total;                 // global row-offset cursor
__device__ int   g_esrc[N_EDGES];         // CSR column (src) array
__device__ __align__(16) half2 g_xh [(size_t)N_NODES * 32];  // x * oisq (128B rows)
__device__ __align__(16) half2 g_h1h[(size_t)N_NODES * 32];  // h1 * oisq
__device__ __align__(16) half  g_W1h[D * D];
__device__ __align__(16) half  g_W2h[D * D];

// ---------------- degree histogram (1 edge/thread, max outstanding) ---------
// counters zero on entry: BSS-zero first call, re-zeroed by k_alloc after.
__global__ void k_deg(const int* __restrict__ src, const int* __restrict__ dst) {
    int e = blockIdx.x * blockDim.x + threadIdx.x;
    if (e >= N_EDGES) return;
    atomicAdd(&g_degOi[src[e]], 1);
    atomicAdd(&g_degIi[dst[e]], 1);
}

// ------- row allocation + norms; zero counters for next replay --------------
__global__ void k_alloc() {
    int i = blockIdx.x * blockDim.x + threadIdx.x;
    if (i >= N_NODES) return;
    int di = g_degIi[i];
    int dO = g_degOi[i];
    int row = atomicAdd(&g_total, di);     // grouping only; order irrelevant
    g_rows[i] = make_int2(row, di);
    g_cursor[i] = row;
    g_oisq[i] = rsqrtf((float)max(dO, 1));
    g_iisq[i] = rsqrtf((float)max(di, 1));
    g_degOi[i] = 0;                        // reset for next replay
    g_degIi[i] = 0;
}

// -- convert x -> fp16 (pre-scaled by oisq); W1/W2 -> fp16; reset total -------
__global__ void k_convert(const float* __restrict__ x,
                          const float* __restrict__ W1,
                          const float* __restrict__ W2) {
    int t = blockIdx.x * blockDim.x + threadIdx.x;
    if (t == 0) g_total = 0;
    if (t < D * D)          g_W1h[t] = __float2half(W1[t]);
    else if (t < 2 * D * D) g_W2h[t - D * D] = __float2half(W2[t - D * D]);
    if (t >= N_NODES * (D / 4)) return;
    int node = t >> 4;                     // 16 float4 per row
    float sc = g_oisq[node];
    float4 v = __ldg((const float4*)x + t);
    g_xh[t * 2 + 0] = __floats2half2_rn(v.x * sc, v.y * sc);
    g_xh[t * 2 + 1] = __floats2half2_rn(v.z * sc, v.w * sc);
}

// ---------------- CSR fill (1 edge/thread, max outstanding atomics) ---------
__global__ void k_fill(const int* __restrict__ src, const int* __restrict__ dst) {
    int e = blockIdx.x * blockDim.x + threadIdx.x;
    if (e >= N_EDGES) return;
    int pos = atomicAdd(&g_cursor[dst[e]], 1);
    g_esrc[pos] = src[e];
}

// =====================================================================
// Fused layers: fp16 gather (4 lanes/node, 8 nodes/warp, unroll x4,
// 8 uint4 in flight/lane) -> half smem -> wmma HMMA -> epilogue
// Block: 256 threads, 64 nodes.
// =====================================================================

#define ACC_U4(V, A)                                                \
    do {                                                            \
        const half2* hv = (const half2*)&(V);                       \
        float2 f0 = __half22float2(hv[0]);                          \
        float2 f1 = __half22float2(hv[1]);                          \
        float2 f2 = __half22float2(hv[2]);                          \
        float2 f3 = __half22float2(hv[3]);                          \
        (A)[0].x += f0.x; (A)[0].y += f0.y;                         \
        (A)[1].x += f1.x; (A)[1].y += f1.y;                         \
        (A)[2].x += f2.x; (A)[2].y += f2.y;                         \
        (A)[3].x += f3.x; (A)[3].y += f3.y;                         \
    } while (0)

// lane l of 4-lane group covers feats [8l,8l+8) and [32+8l,32+8l+8)
__device__ __forceinline__ void group_aggregate(const uint4* __restrict__ feat,
                                                int node, int l,
                                                float2 accA[4], float2 accB[4]) {
    int2 rd = g_rows[node];
    int start = rd.x, deg = rd.y;
    int i = 0;
    int s0 = 0, s1 = 0, s2 = 0, s3 = 0;
    if (deg >= 4) {
        s0 = __ldg(&g_esrc[start + 0]); s1 = __ldg(&g_esrc[start + 1]);
        s2 = __ldg(&g_esrc[start + 2]); s3 = __ldg(&g_esrc[start + 3]);
    }
    while (i + 4 <= deg) {
        int t0 = s0, t1 = s1, t2 = s2, t3 = s3;
        i += 4;
        if (i + 4 <= deg) {                // prefetch next 4 indices
            s0 = __ldg(&g_esrc[start + i + 0]);
            s1 = __ldg(&g_esrc[start + i + 1]);
            s2 = __ldg(&g_esrc[start + i + 2]);
            s3 = __ldg(&g_esrc[start + i + 3]);
        }
        uint4 va0 = __ldg(feat + (size_t)t0 * 8 + l);
        uint4 vb0 = __ldg(feat + (size_t)t0 * 8 + 4 + l);
        uint4 va1 = __ldg(feat + (size_t)t1 * 8 + l);
        uint4 vb1 = __ldg(feat + (size_t)t1 * 8 + 4 + l);
        uint4 va2 = __ldg(feat + (size_t)t2 * 8 + l);
        uint4 vb2 = __ldg(feat + (size_t)t2 * 8 + 4 + l);
        uint4 va3 = __ldg(feat + (size_t)t3 * 8 + l);
        uint4 vb3 = __ldg(feat + (size_t)t3 * 8 + 4 + l);
        ACC_U4(va0, accA); ACC_U4(vb0, accB);
        ACC_U4(va1, accA); ACC_U4(vb1, accB);
        ACC_U4(va2, accA); ACC_U4(vb2, accB);
        ACC_U4(va3, accA); ACC_U4(vb3, accB);
    }
    for (; i < deg; i++) {
        int t0 = __ldg(&g_esrc[start + i]);
        uint4 va0 = __ldg(feat + (size_t)t0 * 8 + l);
        uint4 vb0 = __ldg(feat + (size_t)t0 * 8 + 4 + l);
        ACC_U4(va0, accA); ACC_U4(vb0, accB);
    }
}

// aggregate block's 64 nodes -> half tile sA[64][LDA] (scaled by iisq)
__device__ __forceinline__ void aggregate_phase(const uint4* __restrict__ feat,
                                                int base, int tid, half* sA) {
    int g = tid >> 2, l = tid & 3;
    int gn = base + g;
    float2 accA[4] = {{0,0},{0,0},{0,0},{0,0}};
    float2 accB[4] = {{0,0},{0,0},{0,0},{0,0}};
    if (gn < N_NODES) {
        group_aggregate(feat, gn, l, accA, accB);
        float fi = g_iisq[gn];
#pragma unroll
        for (int j = 0; j < 4; j++) {
            accA[j].x *= fi; accA[j].y *= fi;
            accB[j].x *= fi; accB[j].y *= fi;
        }
    }
    half2 hA[4], hB[4];
#pragma unroll
    for (int j = 0; j < 4; j++) {
        hA[j] = __floats2half2_rn(accA[j].x, accA[j].y);
        hB[j] = __floats2half2_rn(accB[j].x, accB[j].y);
    }
    *(uint4*)&sA[g * LDA + 8 * l]      = *(uint4*)hA;
    *(uint4*)&sA[g * LDA + 32 + 8 * l] = *(uint4*)hB;
}

__device__ __forceinline__ void wmma_gemm(const half* sA, const half* sB,
                                          float* sC, int tid) {
    int w = tid >> 5;
    int mi = w >> 1;
    int ni0 = (w & 1) * 2;
#pragma unroll
    for (int nt = 0; nt < 2; nt++) {
        int ni = ni0 + nt;
        wmma::fragment<wmma::accumulator, 16, 16, 16, float> c;
        wmma::fill_fragment(c, 0.f);
#pragma unroll
        for (int kk = 0; kk < 4; kk++) {
            wmma::fragment<wmma::matrix_a, 16, 16, 16, half, wmma::row_major> a;
            wmma::fragment<wmma::matrix_b, 16, 16, 16, half, wmma::row_major> bf;
            wmma::load_matrix_sync(a, sA + mi * 16 * LDA + kk * 16, LDA);
            wmma::load_matrix_sync(bf, sB + kk * 16 * LDA + ni * 16, LDA);
            wmma::mma_sync(c, a, bf, c);
        }
        wmma::store_matrix_sync(sC + mi * 16 * LDC + ni * 16, c, LDC,
                                wmma::mem_row_major);
    }
}

// Layer 1
__global__ void __launch_bounds__(256) k_layer1(const float* __restrict__ b) {
    __shared__ __align__(16) half  sA[64 * LDA];
    __shared__ __align__(16) half  sB[64 * LDA];
    __shared__ __align__(16) float sC[64 * LDC];
    __shared__ float sBias[D];
    int tid = threadIdx.x;
    int base = blockIdx.x * 64;

    for (int i = tid; i < D * D; i += 256)
        sB[(i >> 6) * LDA + (i & 63)] = g_W1h[i];
    if (tid < D) sBias[tid] = b[tid];

    aggregate_phase((const uint4*)g_xh, base, tid, sA);
    __syncthreads();

    wmma_gemm(sA, sB, sC, tid);
    __syncthreads();

    // epilogue: bias + lrelu + *oisq -> fp16 global
    int g = tid >> 2, q = tid & 3;
    int on = base + g;
    if (on < N_NODES) {
        float sc = __ldg(&g_oisq[on]);
        half2 hv[8];
#pragma unroll
        for (int j = 0; j < 8; j++) {
            int c0 = q * 16 + 2 * j;
            float y0 = sC[g * LDC + c0]     + sBias[c0];
            float y1 = sC[g * LDC + c0 + 1] + sBias[c0 + 1];
            y0 = (y0 > 0.f) ? y0 : NEG_SLOPE * y0;
            y1 = (y1 > 0.f) ? y1 : NEG_SLOPE * y1;
            hv[j] = __floats2half2_rn(y0 * sc, y1 * sc);
        }
        uint4* dstp = (uint4*)&g_h1h[(size_t)on * 32];
        dstp[q * 2 + 0] = ((uint4*)hv)[0];
        dstp[q * 2 + 1] = ((uint4*)hv)[1];
    }
}

// Layer 2 + classifier
__global__ void __launch_bounds__(256) k_layer2(
    const float* __restrict__ b2,
    const float* __restrict__ Wc, const float* __restrict__ bc,
    float* __restrict__ out)
{
    __shared__ __align__(16) half  sA[64 * LDA];
    __shared__ __align__(16) half  sB[64 * LDA];
    __shared__ __align__(16) float sC[64 * LDC];
    __shared__ float sBias[D];
    __shared__ float sWc[D * 2];
    int tid = threadIdx.x;
    int base = blockIdx.x * 64;

    for (int i = tid; i < D * D; i += 256)
        sB[(i >> 6) * LDA + (i & 63)] = g_W2h[i];
    if (tid < D) sBias[tid] = b2[tid];
    if (tid >= 64 && tid < 64 + D * 2) sWc[tid - 64] = Wc[tid - 64];

    aggregate_phase((const uint4*)g_h1h, base, tid, sA);
    __syncthreads();

    wmma_gemm(sA, sB, sC, tid);
    __syncthreads();

    // epilogue: bias + lrelu, in-place in sC (same thread reads/writes)
    int g = tid >> 2, q = tid & 3;
#pragma unroll
    for (int j = 0; j < 16; j++) {
        int c0 = q * 16 + j;
        float y = sC[g * LDC + c0] + sBias[c0];
        y = (y > 0.f) ? y : NEG_SLOPE * y;
        sC[g * LDC + c0] = y;
    }
    __syncthreads();

    // classifier: out[n][c] = bc[c] + sum_k h2[n][k] * Wc[k][c]
    if (tid < 128) {
        int n = tid >> 1, c = tid & 1;
        int on = base + n;
        if (on < N_NODES) {
            float s = bc[c];
#pragma unroll
            for (int k = 0; k < D; k++) s += sC[n * LDC + k] * sWc[k * 2 + c];
            out[(size_t)on * 2 + c] = s;
        }
    }
}

// ---------------- launch ----------------
extern "C" void kernel_launch(void* const* d_in, const int* in_sizes, int n_in,
                              void* d_out, int out_size) {
    const float* x   = (const float*)d_in[0];
    const int*   src = (const int*)  d_in[1];
    const int*   dst = (const int*)  d_in[2];
    const float* W1  = (const float*)d_in[3];
    const float* b1  = (const float*)d_in[4];
    const float* W2  = (const float*)d_in[5];
    const float* b2  = (const float*)d_in[6];
    const float* Wc  = (const float*)d_in[7];
    const float* bc  = (const float*)d_in[8];
    float* out = (float*)d_out;

    k_deg    <<<(N_EDGES + 255) / 256, 256>>>(src, dst);
    k_alloc  <<<(N_NODES + 255) / 256, 256>>>();
    k_convert<<<(N_NODES * (D / 4) + 255) / 256, 256>>>(x, W1, W2);
    k_fill   <<<(N_EDGES + 255) / 256, 256>>>(src, dst);

    k_layer1<<<(N_NODES + 63) / 64, 256>>>(b1);
    k_layer2<<<(N_NODES + 63) / 64, 256>>>(b2, Wc, bc, out);
}

// round 12
// speedup vs baseline: 1.2191x; 1.0325x over previous
#include <cuda_runtime.h>
#include <cuda_fp16.h>
#include <mma.h>
#include <cstdint>

using namespace nvcuda;

#define N_NODES 100000
#define N_EDGES 1000000
#define D 64
#define NEG_SLOPE 0.01f

#define LDA 72   // half leading dim for A/B tiles
#define LDC 68   // float leading dim for C tile
#define ESRC_CAP (N_EDGES + 3 * N_NODES + 64)   // padded CSR capacity

// ---------------- scratch (no allocations allowed) ----------------
__device__ int   g_degOi[N_NODES];
__device__ int   g_degIi[N_NODES];
__device__ float g_oisq [N_NODES];
__device__ float g_iisq [N_NODES];
__device__ int   g_rowptr[N_NODES];       // padded CSR row start
__device__ int2  g_rows [N_NODES];        // {padded start, n4 = ceil(deg/4)}
__device__ int   g_rankE[N_EDGES];        // intra-node rank of each edge
__device__ int   g_total;                 // global row-offset cursor
__device__ __align__(16) int g_esrc[ESRC_CAP];   // CSR column (src), padded rows
__device__ __align__(16) half2 g_xh [((size_t)N_NODES + 1) * 32]; // x*oisq (+zero row)
__device__ __align__(16) half2 g_h1h[((size_t)N_NODES + 1) * 32]; // h1*oisq (+zero row)
__device__ __align__(16) half  g_W1h[D * D];
__device__ __align__(16) half  g_W2h[D * D];

// ------- degree histogram + rank capture (1 edge/thread) --------------------
// counters zero on entry: BSS-zero first call, re-zeroed by k_alloc after.
__global__ void k_deg(const int* __restrict__ src, const int* __restrict__ dst) {
    int e = blockIdx.x * blockDim.x + threadIdx.x;
    if (e >= N_EDGES) return;
    atomicAdd(&g_degOi[src[e]], 1);                    // no-return -> RED
    g_rankE[e] = atomicAdd(&g_degIi[dst[e]], 1);       // rank within dst row
}

// ------- padded row allocation + norms + pad fill; zero counters ------------
__global__ void k_alloc() {
    int i = blockIdx.x * blockDim.x + threadIdx.x;
    if (i >= N_NODES) return;
    int di = g_degIi[i];
    int dO = g_degOi[i];
    int padded = (di + 3) & ~3;
    int row = atomicAdd(&g_total, padded);   // grouping only; order irrelevant
    g_rowptr[i] = row;
    g_rows[i] = make_int2(row, padded >> 2);
    g_oisq[i] = rsqrtf((float)max(dO, 1));
    g_iisq[i] = rsqrtf((float)max(di, 1));
    for (int p = di; p < padded; p++) g_esrc[row + p] = N_NODES;  // dummy zero row
    g_degOi[i] = 0;                          // reset for next replay
    g_degIi[i] = 0;
}

// -- convert x -> fp16 (pre-scaled by oisq); W1/W2 -> fp16; reset total -------
__global__ void k_convert(const float* __restrict__ x,
                          const float* __restrict__ W1,
                          const float* __restrict__ W2) {
    int t = blockIdx.x * blockDim.x + threadIdx.x;
    if (t == 0) g_total = 0;
    if (t < D * D)          g_W1h[t] = __float2half(W1[t]);
    else if (t < 2 * D * D) g_W2h[t - D * D] = __float2half(W2[t - D * D]);
    if (t >= N_NODES * (D / 4)) return;
    int node = t >> 4;                       // 16 float4 per row
    float sc = g_oisq[node];
    float4 v = __ldg((const float4*)x + t);
    g_xh[t * 2 + 0] = __floats2half2_rn(v.x * sc, v.y * sc);
    g_xh[t * 2 + 1] = __floats2half2_rn(v.z * sc, v.w * sc);
}

// ---------------- CSR fill: NO atomics (rank precomputed) -------------------
__global__ void k_fill(const int* __restrict__ src, const int* __restrict__ dst) {
    int e = blockIdx.x * blockDim.x + threadIdx.x;
    if (e >= N_EDGES) return;
    int pos = __ldg(&g_rowptr[dst[e]]) + g_rankE[e];
    pos = min(pos, ESRC_CAP - 1);            // provable no-op; OOB guard
    g_esrc[pos] = src[e];
}

// =====================================================================
// Fused layers: fp16 gather (4 lanes/node, 8 nodes/warp), padded rows,
// int4 index loads, no tail -> half smem -> wmma HMMA -> epilogue
// Block: 256 threads, 64 nodes.
// =====================================================================

#define ACC_U4(V, A)                                                \
    do {                                                            \
        const half2* hv = (const half2*)&(V);                       \
        float2 f0 = __half22float2(hv[0]);                          \
        float2 f1 = __half22float2(hv[1]);                          \
        float2 f2 = __half22float2(hv[2]);                          \
        float2 f3 = __half22float2(hv[3]);                          \
        (A)[0].x += f0.x; (A)[0].y += f0.y;                         \
        (A)[1].x += f1.x; (A)[1].y += f1.y;                         \
        (A)[2].x += f2.x; (A)[2].y += f2.y;                         \
        (A)[3].x += f3.x; (A)[3].y += f3.y;                         \
    } while (0)

// lane l of 4-lane group covers feats [8l,8l+8) and [32+8l,32+8l+8)
__device__ __forceinline__ void group_aggregate(const uint4* __restrict__ feat,
                                                int node, int l,
                                                float2 accA[4], float2 accB[4]) {
    int2 rd = g_rows[node];
    int start = rd.x, n4 = rd.y;
    if (n4 == 0) return;
    const int4* ip = (const int4*)(g_esrc + start);   // 16B-aligned (padded rows)
    int4 idx = __ldg(ip);
    for (int k = 1; ; k++) {
        int4 cur = idx;
        if (k < n4) idx = __ldg(ip + k);              // prefetch next 4 indices
        uint4 va0 = __ldg(feat + (size_t)cur.x * 8 + l);
        uint4 vb0 = __ldg(feat + (size_t)cur.x * 8 + 4 + l);
        uint4 va1 = __ldg(feat + (size_t)cur.y * 8 + l);
        uint4 vb1 = __ldg(feat + (size_t)cur.y * 8 + 4 + l);
        uint4 va2 = __ldg(feat + (size_t)cur.z * 8 + l);
        uint4 vb2 = __ldg(feat + (size_t)cur.z * 8 + 4 + l);
        uint4 va3 = __ldg(feat + (size_t)cur.w * 8 + l);
        uint4 vb3 = __ldg(feat + (size_t)cur.w * 8 + 4 + l);
        ACC_U4(va0, accA); ACC_U4(vb0, accB);
        ACC_U4(va1, accA); ACC_U4(vb1, accB);
        ACC_U4(va2, accA); ACC_U4(vb2, accB);
        ACC_U4(va3, accA); ACC_U4(vb3, accB);
        if (k >= n4) break;
    }
}

// aggregate block's 64 nodes -> half tile sA[64][LDA] (scaled by iisq)
__device__ __forceinline__ void aggregate_phase(const uint4* __restrict__ feat,
                                                int base, int tid, half* sA) {
    int g = tid >> 2, l = tid & 3;
    int gn = base + g;
    float2 accA[4] = {{0,0},{0,0},{0,0},{0,0}};
    float2 accB[4] = {{0,0},{0,0},{0,0},{0,0}};
    if (gn < N_NODES) {
        group_aggregate(feat, gn, l, accA, accB);
        float fi = g_iisq[gn];
#pragma unroll
        for (int j = 0; j < 4; j++) {
            accA[j].x *= fi; accA[j].y *= fi;
            accB[j].x *= fi; accB[j].y *= fi;
        }
    }
    half2 hA[4], hB[4];
#pragma unroll
    for (int j = 0; j < 4; j++) {
        hA[j] = __floats2half2_rn(accA[j].x, accA[j].y);
        hB[j] = __floats2half2_rn(accB[j].x, accB[j].y);
    }
    *(uint4*)&sA[g * LDA + 8 * l]      = *(uint4*)hA;
    *(uint4*)&sA[g * LDA + 32 + 8 * l] = *(uint4*)hB;
}

__device__ __forceinline__ void wmma_gemm(const half* sA, const half* sB,
                                          float* sC, int tid) {
    int w = tid >> 5;
    int mi = w >> 1;
    int ni0 = (w & 1) * 2;
#pragma unroll
    for (int nt = 0; nt < 2; nt++) {
        int ni = ni0 + nt;
        wmma::fragment<wmma::accumulator, 16, 16, 16, float> c;
        wmma::fill_fragment(c, 0.f);
#pragma unroll
        for (int kk = 0; kk < 4; kk++) {
            wmma::fragment<wmma::matrix_a, 16, 16, 16, half, wmma::row_major> a;
            wmma::fragment<wmma::matrix_b, 16, 16, 16, half, wmma::row_major> bf;
            wmma::load_matrix_sync(a, sA + mi * 16 * LDA + kk * 16, LDA);
            wmma::load_matrix_sync(bf, sB + kk * 16 * LDA + ni * 16, LDA);
            wmma::mma_sync(c, a, bf, c);
        }
        wmma::store_matrix_sync(sC + mi * 16 * LDC + ni * 16, c, LDC,
                                wmma::mem_row_major);
    }
}

// Layer 1
__global__ void __launch_bounds__(256) k_layer1(const float* __restrict__ b) {
    __shared__ __align__(16) half  sA[64 * LDA];
    __shared__ __align__(16) half  sB[64 * LDA];
    __shared__ __align__(16) float sC[64 * LDC];
    __shared__ float sBias[D];
    int tid = threadIdx.x;
    int base = blockIdx.x * 64;

    for (int i = tid; i < D * D; i += 256)
        sB[(i >> 6) * LDA + (i & 63)] = g_W1h[i];
    if (tid < D) sBias[tid] = b[tid];

    aggregate_phase((const uint4*)g_xh, base, tid, sA);
    __syncthreads();

    wmma_gemm(sA, sB, sC, tid);
    __syncthreads();

    // epilogue: bias + lrelu + *oisq -> fp16 global
    int g = tid >> 2, q = tid & 3;
    int on = base + g;
    if (on < N_NODES) {
        float sc = __ldg(&g_oisq[on]);
        half2 hv[8];
#pragma unroll
        for (int j = 0; j < 8; j++) {
            int c0 = q * 16 + 2 * j;
            float y0 = sC[g * LDC + c0]     + sBias[c0];
            float y1 = sC[g * LDC + c0 + 1] + sBias[c0 + 1];
            y0 = (y0 > 0.f) ? y0 : NEG_SLOPE * y0;
            y1 = (y1 > 0.f) ? y1 : NEG_SLOPE * y1;
            hv[j] = __floats2half2_rn(y0 * sc, y1 * sc);
        }
        uint4* dstp = (uint4*)&g_h1h[(size_t)on * 32];
        dstp[q * 2 + 0] = ((uint4*)hv)[0];
        dstp[q * 2 + 1] = ((uint4*)hv)[1];
    }
}

// Layer 2 + classifier
__global__ void __launch_bounds__(256) k_layer2(
    const float* __restrict__ b2,
    const float* __restrict__ Wc, const float* __restrict__ bc,
    float* __restrict__ out)
{
    __shared__ __align__(16) half  sA[64 * LDA];
    __shared__ __align__(16) half  sB[64 * LDA];
    __shared__ __align__(16) float sC[64 * LDC];
    __shared__ float sBias[D];
    __shared__ float sWc[D * 2];
    int tid = threadIdx.x;
    int base = blockIdx.x * 64;

    for (int i = tid; i < D * D; i += 256)
        sB[(i >> 6) * LDA + (i & 63)] = g_W2h[i];
    if (tid < D) sBias[tid] = b2[tid];
    if (tid >= 64 && tid < 64 + D * 2) sWc[tid - 64] = Wc[tid - 64];

    aggregate_phase((const uint4*)g_h1h, base, tid, sA);
    __syncthreads();

    wmma_gemm(sA, sB, sC, tid);
    __syncthreads();

    // epilogue: bias + lrelu, in-place in sC (same thread reads/writes)
    int g = tid >> 2, q = tid & 3;
#pragma unroll
    for (int j = 0; j < 16; j++) {
        int c0 = q * 16 + j;
        float y = sC[g * LDC + c0] + sBias[c0];
        y = (y > 0.f) ? y : NEG_SLOPE * y;
        sC[g * LDC + c0] = y;
    }
    __syncthreads();

    // classifier: out[n][c] = bc[c] + sum_k h2[n][k] * Wc[k][c]
    if (tid < 128) {
        int n = tid >> 1, c = tid & 1;
        int on = base + n;
        if (on < N_NODES) {
            float s = bc[c];
#pragma unroll
            for (int k = 0; k < D; k++) s += sC[n * LDC + k] * sWc[k * 2 + c];
            out[(size_t)on * 2 + c] = s;
        }
    }
}

// ---------------- launch ----------------
extern "C" void kernel_launch(void* const* d_in, const int* in_sizes, int n_in,
                              void* d_out, int out_size) {
    const float* x   = (const float*)d_in[0];
    const int*   src = (const int*)  d_in[1];
    const int*   dst = (const int*)  d_in[2];
    const float* W1  = (const float*)d_in[3];
    const float* b1  = (const float*)d_in[4];
    const float* W2  = (const float*)d_in[5];
    const float* b2  = (const float*)d_in[6];
    const float* Wc  = (const float*)d_in[7];
    const float* bc  = (const float*)d_in[8];
    float* out = (float*)d_out;

    k_deg    <<<(N_EDGES + 255) / 256, 256>>>(src, dst);
    k_alloc  <<<(N_NODES + 255) / 256, 256>>>();
    k_convert<<<(N_NODES * (D / 4) + 255) / 256, 256>>>(x, W1, W2);
    k_fill   <<<(N_EDGES + 255) / 256, 256>>>(src, dst);

    k_layer1<<<(N_NODES + 63) / 64, 256>>>(b1);
    k_layer2<<<(N_NODES + 63) / 64, 256>>>(b2, Wc, bc, out);
}

// round 13
// speedup vs baseline: 1.2283x; 1.0075x over previous
#include <cuda_runtime.h>
#include <cuda_fp16.h>
#include <mma.h>
#include <cstdint>

using namespace nvcuda;

#define N_NODES 100000
#define N_EDGES 1000000
#define D 64
#define NEG_SLOPE 0.01f

#define LDA 72   // half leading dim for A/B tiles
#define LDC 68   // float leading dim for C tile
#define ESRC_CAP (N_EDGES + 3 * N_NODES + 64)   // padded CSR capacity

// ---------------- scratch (no allocations allowed) ----------------
__device__ int   g_degOi[N_NODES];
__device__ int   g_degIi[N_NODES];
__device__ float g_oisq [N_NODES];
__device__ float g_iisq [N_NODES];
__device__ int   g_rowptr[N_NODES];       // padded CSR row start
__device__ int2  g_rows [N_NODES];        // {padded start, n4 = ceil(deg/4)}
__device__ int   g_rankE[N_EDGES];        // intra-node rank of each edge
__device__ int   g_total;                 // global row-offset cursor
__device__ __align__(16) int g_esrc[ESRC_CAP];   // CSR column (src), padded rows
__device__ __align__(16) half2 g_xh [((size_t)N_NODES + 1) * 32]; // x*oisq (+zero row)
__device__ __align__(16) half2 g_h1h[((size_t)N_NODES + 1) * 32]; // h1*oisq (+zero row)
__device__ __align__(16) half  g_W1h[D * D];
__device__ __align__(16) half  g_W2h[D * D];

// ------- degree histogram + rank capture (1 edge/thread) --------------------
// counters zero on entry: BSS-zero first call, re-zeroed by k_alloc after.
__global__ void k_deg(const int* __restrict__ src, const int* __restrict__ dst) {
    int e = blockIdx.x * blockDim.x + threadIdx.x;
    if (e >= N_EDGES) return;
    atomicAdd(&g_degOi[src[e]], 1);                    // no-return -> RED
    g_rankE[e] = atomicAdd(&g_degIi[dst[e]], 1);       // rank within dst row
}

// ------- padded row allocation + norms + pad fill; zero counters ------------
__global__ void k_alloc() {
    int i = blockIdx.x * blockDim.x + threadIdx.x;
    if (i >= N_NODES) return;
    int di = g_degIi[i];
    int dO = g_degOi[i];
    int padded = (di + 3) & ~3;
    int row = atomicAdd(&g_total, padded);   // grouping only; order irrelevant
    g_rowptr[i] = row;
    g_rows[i] = make_int2(row, padded >> 2);
    g_oisq[i] = rsqrtf((float)max(dO, 1));
    g_iisq[i] = rsqrtf((float)max(di, 1));
    for (int p = di; p < padded; p++) g_esrc[row + p] = N_NODES;  // dummy zero row
    g_degOi[i] = 0;                          // reset for next replay
    g_degIi[i] = 0;
}

// -- fused: CSR fill (no atomics) + x->fp16 convert + W->fp16; reset total ----
// Both halves depend only on k_alloc and bind different resources
// (fill: random L2; convert: DRAM stream) -> overlap in one launch.
__global__ void k_convfill(const float* __restrict__ x,
                           const float* __restrict__ W1,
                           const float* __restrict__ W2,
                           const int* __restrict__ src,
                           const int* __restrict__ dst) {
    int t = blockIdx.x * blockDim.x + threadIdx.x;
    if (t == 0) g_total = 0;
    if (t < D * D)          g_W1h[t] = __float2half(W1[t]);
    else if (t < 2 * D * D) g_W2h[t - D * D] = __float2half(W2[t - D * D]);

    if (t < N_EDGES) {                       // CSR fill: rank precomputed
        int pos = __ldg(&g_rowptr[dst[t]]) + g_rankE[t];
        pos = min(pos, ESRC_CAP - 1);        // provable no-op; OOB guard
        g_esrc[pos] = src[t];
    }
    if (t < N_NODES * (D / 4)) {             // convert 1 float4 -> 2 half2
        int node = t >> 4;                   // 16 float4 per row
        float sc = g_oisq[node];
        float4 v = __ldg((const float4*)x + t);
        g_xh[t * 2 + 0] = __floats2half2_rn(v.x * sc, v.y * sc);
        g_xh[t * 2 + 1] = __floats2half2_rn(v.z * sc, v.w * sc);
    }
}

// =====================================================================
// Fused layers: fp16 gather (4 lanes/node, 8 nodes/warp), padded rows,
// int4 index loads, no tail -> half smem -> wmma HMMA -> epilogue
// Block: 256 threads, 64 nodes.
// =====================================================================

#define ACC_U4(V, A)                                                \
    do {                                                            \
        const half2* hv = (const half2*)&(V);                       \
        float2 f0 = __half22float2(hv[0]);                          \
        float2 f1 = __half22float2(hv[1]);                          \
        float2 f2 = __half22float2(hv[2]);                          \
        float2 f3 = __half22float2(hv[3]);                          \
        (A)[0].x += f0.x; (A)[0].y += f0.y;                         \
        (A)[1].x += f1.x; (A)[1].y += f1.y;                         \
        (A)[2].x += f2.x; (A)[2].y += f2.y;                         \
        (A)[3].x += f3.x; (A)[3].y += f3.y;                         \
    } while (0)

// lane l of 4-lane group covers feats [8l,8l+8) and [32+8l,32+8l+8)
__device__ __forceinline__ void group_aggregate(const uint4* __restrict__ feat,
                                                int node, int l,
                                                float2 accA[4], float2 accB[4]) {
    int2 rd = g_rows[node];
    int start = rd.x, n4 = rd.y;
    if (n4 == 0) return;
    const int4* ip = (const int4*)(g_esrc + start);   // 16B-aligned (padded rows)
    int4 idx = __ldg(ip);
    for (int k = 1; ; k++) {
        int4 cur = idx;
        if (k < n4) idx = __ldg(ip + k);              // prefetch next 4 indices
        uint4 va0 = __ldg(feat + (size_t)cur.x * 8 + l);
        uint4 vb0 = __ldg(feat + (size_t)cur.x * 8 + 4 + l);
        uint4 va1 = __ldg(feat + (size_t)cur.y * 8 + l);
        uint4 vb1 = __ldg(feat + (size_t)cur.y * 8 + 4 + l);
        uint4 va2 = __ldg(feat + (size_t)cur.z * 8 + l);
        uint4 vb2 = __ldg(feat + (size_t)cur.z * 8 + 4 + l);
        uint4 va3 = __ldg(feat + (size_t)cur.w * 8 + l);
        uint4 vb3 = __ldg(feat + (size_t)cur.w * 8 + 4 + l);
        ACC_U4(va0, accA); ACC_U4(vb0, accB);
        ACC_U4(va1, accA); ACC_U4(vb1, accB);
        ACC_U4(va2, accA); ACC_U4(vb2, accB);
        ACC_U4(va3, accA); ACC_U4(vb3, accB);
        if (k >= n4) break;
    }
}

// aggregate block's 64 nodes -> half tile sA[64][LDA] (scaled by iisq)
__device__ __forceinline__ void aggregate_phase(const uint4* __restrict__ feat,
                                                int base, int tid, half* sA) {
    int g = tid >> 2, l = tid & 3;
    int gn = base + g;
    float2 accA[4] = {{0,0},{0,0},{0,0},{0,0}};
    float2 accB[4] = {{0,0},{0,0},{0,0},{0,0}};
    if (gn < N_NODES) {
        group_aggregate(feat, gn, l, accA, accB);
        float fi = g_iisq[gn];
#pragma unroll
        for (int j = 0; j < 4; j++) {
            accA[j].x *= fi; accA[j].y *= fi;
            accB[j].x *= fi; accB[j].y *= fi;
        }
    }
    half2 hA[4], hB[4];
#pragma unroll
    for (int j = 0; j < 4; j++) {
        hA[j] = __floats2half2_rn(accA[j].x, accA[j].y);
        hB[j] = __floats2half2_rn(accB[j].x, accB[j].y);
    }
    *(uint4*)&sA[g * LDA + 8 * l]      = *(uint4*)hA;
    *(uint4*)&sA[g * LDA + 32 + 8 * l] = *(uint4*)hB;
}

__device__ __forceinline__ void wmma_gemm(const half* sA, const half* sB,
                                          float* sC, int tid) {
    int w = tid >> 5;
    int mi = w >> 1;
    int ni0 = (w & 1) * 2;
#pragma unroll
    for (int nt = 0; nt < 2; nt++) {
        int ni = ni0 + nt;
        wmma::fragment<wmma::accumulator, 16, 16, 16, float> c;
        wmma::fill_fragment(c, 0.f);
#pragma unroll
        for (int kk = 0; kk < 4; kk++) {
            wmma::fragment<wmma::matrix_a, 16, 16, 16, half, wmma::row_major> a;
            wmma::fragment<wmma::matrix_b, 16, 16, 16, half, wmma::row_major> bf;
            wmma::load_matrix_sync(a, sA + mi * 16 * LDA + kk * 16, LDA);
            wmma::load_matrix_sync(bf, sB + kk * 16 * LDA + ni * 16, LDA);
            wmma::mma_sync(c, a, bf, c);
        }
        wmma::store_matrix_sync(sC + mi * 16 * LDC + ni * 16, c, LDC,
                                wmma::mem_row_major);
    }
}

// Layer 1
__global__ void __launch_bounds__(256) k_layer1(const float* __restrict__ b) {
    __shared__ __align__(16) half  sA[64 * LDA];
    __shared__ __align__(16) half  sB[64 * LDA];
    __shared__ __align__(16) float sC[64 * LDC];
    __shared__ float sBias[D];
    int tid = threadIdx.x;
    int base = blockIdx.x * 64;

    for (int i = tid; i < D * D; i += 256)
        sB[(i >> 6) * LDA + (i & 63)] = g_W1h[i];
    if (tid < D) sBias[tid] = b[tid];

    aggregate_phase((const uint4*)g_xh, base, tid, sA);
    __syncthreads();

    wmma_gemm(sA, sB, sC, tid);
    __syncthreads();

    // epilogue: bias + lrelu + *oisq -> fp16 global
    int g = tid >> 2, q = tid & 3;
    int on = base + g;
    if (on < N_NODES) {
        float sc = __ldg(&g_oisq[on]);
        half2 hv[8];
#pragma unroll
        for (int j = 0; j < 8; j++) {
            int c0 = q * 16 + 2 * j;
            float y0 = sC[g * LDC + c0]     + sBias[c0];
            float y1 = sC[g * LDC + c0 + 1] + sBias[c0 + 1];
            y0 = (y0 > 0.f) ? y0 : NEG_SLOPE * y0;
            y1 = (y1 > 0.f) ? y1 : NEG_SLOPE * y1;
            hv[j] = __floats2half2_rn(y0 * sc, y1 * sc);
        }
        uint4* dstp = (uint4*)&g_h1h[(size_t)on * 32];
        dstp[q * 2 + 0] = ((uint4*)hv)[0];
        dstp[q * 2 + 1] = ((uint4*)hv)[1];
    }
}

// Layer 2 + classifier
__global__ void __launch_bounds__(256) k_layer2(
    const float* __restrict__ b2,
    const float* __restrict__ Wc, const float* __restrict__ bc,
    float* __restrict__ out)
{
    __shared__ __align__(16) half  sA[64 * LDA];
    __shared__ __align__(16) half  sB[64 * LDA];
    __shared__ __align__(16) float sC[64 * LDC];
    __shared__ float sBias[D];
    __shared__ float sWc[D * 2];
    int tid = threadIdx.x;
    int base = blockIdx.x * 64;

    for (int i = tid; i < D * D; i += 256)
        sB[(i >> 6) * LDA + (i & 63)] = g_W2h[i];
    if (tid < D) sBias[tid] = b2[tid];
    if (tid >= 64 && tid < 64 + D * 2) sWc[tid - 64] = Wc[tid - 64];

    aggregate_phase((const uint4*)g_h1h, base, tid, sA);
    __syncthreads();

    wmma_gemm(sA, sB, sC, tid);
    __syncthreads();

    // epilogue: bias + lrelu, in-place in sC (same thread reads/writes)
    int g = tid >> 2, q = tid & 3;
#pragma unroll
    for (int j = 0; j < 16; j++) {
        int c0 = q * 16 + j;
        float y = sC[g * LDC + c0] + sBias[c0];
        y = (y > 0.f) ? y : NEG_SLOPE * y;
        sC[g * LDC + c0] = y;
    }
    __syncthreads();

    // classifier: out[n][c] = bc[c] + sum_k h2[n][k] * Wc[k][c]
    if (tid < 128) {
        int n = tid >> 1, c = tid & 1;
        int on = base + n;
        if (on < N_NODES) {
            float s = bc[c];
#pragma unroll
            for (int k = 0; k < D; k++) s += sC[n * LDC + k] * sWc[k * 2 + c];
            out[(size_t)on * 2 + c] = s;
        }
    }
}

// ---------------- launch ----------------
extern "C" void kernel_launch(void* const* d_in, const int* in_sizes, int n_in,
                              void* d_out, int out_size) {
    const float* x   = (const float*)d_in[0];
    const int*   src = (const int*)  d_in[1];
    const int*   dst = (const int*)  d_in[2];
    const float* W1  = (const float*)d_in[3];
    const float* b1  = (const float*)d_in[4];
    const float* W2  = (const float*)d_in[5];
    const float* b2  = (const float*)d_in[6];
    const float* Wc  = (const float*)d_in[7];
    const float* bc  = (const float*)d_in[8];
    float* out = (float*)d_out;

    k_deg     <<<(N_EDGES + 255) / 256, 256>>>(src, dst);
    k_alloc   <<<(N_NODES + 255) / 256, 256>>>();
    k_convfill<<<(N_NODES * (D / 4) + 255) / 256, 256>>>(x, W1, W2, src, dst);

    k_layer1<<<(N_NODES + 63) / 64, 256>>>(b1);
    k_layer2<<<(N_NODES + 63) / 64, 256>>>(b2, Wc, bc, out);
}

// round 14
// speedup vs baseline: 1.2735x; 1.0368x over previous
#include <cuda_runtime.h>
#include <cuda_fp16.h>
#include <mma.h>
#include <cstdint>

using namespace nvcuda;

#define N_NODES 100000
#define N_EDGES 1000000
#define D 64
#define NEG_SLOPE 0.01f

#define LDA 72   // half leading dim for A/B tiles
#define LDC 68   // float leading dim for C tile
#define ESRC_CAP (N_EDGES + 3 * N_NODES + 64)   // padded CSR capacity

// ---------------- scratch (no allocations allowed) ----------------
__device__ int   g_degOi[N_NODES];
__device__ int   g_degIi[N_NODES];
__device__ float g_oisq [N_NODES];
__device__ float g_iisq [N_NODES];
__device__ int   g_rowptr[N_NODES];       // padded CSR row start
__device__ int2  g_rows [N_NODES];        // {padded start, n4 = ceil(deg/4)}
__device__ int   g_rankE[N_EDGES];        // intra-node rank of each edge
__device__ int   g_total;                 // global row-offset cursor
__device__ __align__(16) int g_esrc[ESRC_CAP];   // CSR column (src), padded rows
__device__ __align__(16) half2 g_xh [((size_t)N_NODES + 1) * 32]; // x*oisq (+zero row)
__device__ __align__(16) half2 g_h1h[((size_t)N_NODES + 1) * 32]; // h1*oisq (+zero row)
__device__ __align__(16) half  g_W1h[D * D];
__device__ __align__(16) half  g_W2h[D * D];

// ------- degree histogram + rank capture (1 edge/thread) --------------------
// counters zero on entry: BSS-zero first call, re-zeroed by k_alloc after.
__global__ void k_deg(const int* __restrict__ src, const int* __restrict__ dst) {
    int e = blockIdx.x * blockDim.x + threadIdx.x;
    if (e >= N_EDGES) return;
    atomicAdd(&g_degOi[src[e]], 1);                    // no-return -> RED
    g_rankE[e] = atomicAdd(&g_degIi[dst[e]], 1);       // rank within dst row
}

// ------- padded row allocation + norms + pad fill; zero counters ------------
__global__ void k_alloc() {
    int i = blockIdx.x * blockDim.x + threadIdx.x;
    if (i >= N_NODES) return;
    int di = g_degIi[i];
    int dO = g_degOi[i];
    int padded = (di + 3) & ~3;
    int row = atomicAdd(&g_total, padded);   // grouping only; order irrelevant
    g_rowptr[i] = row;
    g_rows[i] = make_int2(row, padded >> 2);
    g_oisq[i] = rsqrtf((float)max(dO, 1));
    g_iisq[i] = rsqrtf((float)max(di, 1));
    for (int p = di; p < padded; p++) g_esrc[row + p] = N_NODES;  // dummy zero row
    g_degOi[i] = 0;                          // reset for next replay
    g_degIi[i] = 0;
}

// -- fused: CSR fill (no atomics) + x->fp16 convert + W->fp16; reset total ----
__global__ void k_convfill(const float* __restrict__ x,
                           const float* __restrict__ W1,
                           const float* __restrict__ W2,
                           const int* __restrict__ src,
                           const int* __restrict__ dst) {
    int t = blockIdx.x * blockDim.x + threadIdx.x;
    if (t == 0) g_total = 0;
    if (t < D * D)          g_W1h[t] = __float2half(W1[t]);
    else if (t < 2 * D * D) g_W2h[t - D * D] = __float2half(W2[t - D * D]);

    if (t < N_EDGES) {                       // CSR fill: rank precomputed
        int pos = __ldg(&g_rowptr[dst[t]]) + g_rankE[t];
        pos = min(pos, ESRC_CAP - 1);        // provable no-op; OOB guard
        g_esrc[pos] = src[t];
    }
    if (t < N_NODES * (D / 4)) {             // convert 1 float4 -> 2 half2
        int node = t >> 4;                   // 16 float4 per row
        float sc = g_oisq[node];
        float4 v = __ldg((const float4*)x + t);
        g_xh[t * 2 + 0] = __floats2half2_rn(v.x * sc, v.y * sc);
        g_xh[t * 2 + 1] = __floats2half2_rn(v.z * sc, v.w * sc);
    }
}

// =====================================================================
// Fused layers: fp16 gather (8 lanes/node, 4 nodes/warp), padded rows,
// int4 index loads -> half smem -> wmma HMMA (16 warps, 1 tile each)
// Block: 512 threads, 64 nodes. Low regs -> 3 blocks/SM (75% occ).
// =====================================================================

#define ACC_U4(V, A)                                                \
    do {                                                            \
        const half2* hv = (const half2*)&(V);                       \
        float2 f0 = __half22float2(hv[0]);                          \
        float2 f1 = __half22float2(hv[1]);                          \
        float2 f2 = __half22float2(hv[2]);                          \
        float2 f3 = __half22float2(hv[3]);                          \
        (A)[0].x += f0.x; (A)[0].y += f0.y;                         \
        (A)[1].x += f1.x; (A)[1].y += f1.y;                         \
        (A)[2].x += f2.x; (A)[2].y += f2.y;                         \
        (A)[3].x += f3.x; (A)[3].y += f3.y;                         \
    } while (0)

// lane l (0..7) of a node-group covers feats [8l, 8l+8) = one uint4
__device__ __forceinline__ void group_aggregate(const uint4* __restrict__ feat,
                                                int node, int l,
                                                float2 acc[4]) {
    int2 rd = g_rows[node];
    int start = rd.x, n4 = rd.y;
    if (n4 == 0) return;
    const int4* ip = (const int4*)(g_esrc + start);   // 16B-aligned (padded rows)
    int4 idx = __ldg(ip);
    for (int k = 1; ; k++) {
        int4 cur = idx;
        if (k < n4) idx = __ldg(ip + k);              // prefetch next 4 indices
        uint4 v0 = __ldg(feat + (size_t)cur.x * 8 + l);
        uint4 v1 = __ldg(feat + (size_t)cur.y * 8 + l);
        uint4 v2 = __ldg(feat + (size_t)cur.z * 8 + l);
        uint4 v3 = __ldg(feat + (size_t)cur.w * 8 + l);
        ACC_U4(v0, acc);
        ACC_U4(v1, acc);
        ACC_U4(v2, acc);
        ACC_U4(v3, acc);
        if (k >= n4) break;
    }
}

// aggregate block's 64 nodes -> half tile sA[64][LDA] (scaled by iisq)
__device__ __forceinline__ void aggregate_phase(const uint4* __restrict__ feat,
                                                int base, int tid, half* sA) {
    int g = tid >> 3, l = tid & 7;          // 64 groups x 8 lanes
    int gn = base + g;
    float2 acc[4] = {{0,0},{0,0},{0,0},{0,0}};
    if (gn < N_NODES) {
        group_aggregate(feat, gn, l, acc);
        float fi = g_iisq[gn];
#pragma unroll
        for (int j = 0; j < 4; j++) { acc[j].x *= fi; acc[j].y *= fi; }
    }
    half2 h[4];
#pragma unroll
    for (int j = 0; j < 4; j++) h[j] = __floats2half2_rn(acc[j].x, acc[j].y);
    *(uint4*)&sA[g * LDA + 8 * l] = *(uint4*)h;
}

// 16 warps, one 16x16 tile each: sC = sA @ sB
__device__ __forceinline__ void wmma_gemm(const half* sA, const half* sB,
                                          float* sC, int tid) {
    int w = tid >> 5;                        // 0..15
    int mi = w >> 2, ni = w & 3;
    wmma::fragment<wmma::accumulator, 16, 16, 16, float> c;
    wmma::fill_fragment(c, 0.f);
#pragma unroll
    for (int kk = 0; kk < 4; kk++) {
        wmma::fragment<wmma::matrix_a, 16, 16, 16, half, wmma::row_major> a;
        wmma::fragment<wmma::matrix_b, 16, 16, 16, half, wmma::row_major> bf;
        wmma::load_matrix_sync(a, sA + mi * 16 * LDA + kk * 16, LDA);
        wmma::load_matrix_sync(bf, sB + kk * 16 * LDA + ni * 16, LDA);
        wmma::mma_sync(c, a, bf, c);
    }
    wmma::store_matrix_sync(sC + mi * 16 * LDC + ni * 16, c, LDC,
                            wmma::mem_row_major);
}

// Layer 1
__global__ void __launch_bounds__(512, 3) k_layer1(const float* __restrict__ b) {
    __shared__ __align__(16) half  sA[64 * LDA];
    __shared__ __align__(16) half  sB[64 * LDA];
    __shared__ __align__(16) float sC[64 * LDC];
    __shared__ float sBias[D];
    int tid = threadIdx.x;
    int base = blockIdx.x * 64;

    for (int i = tid; i < D * D; i += 512)
        sB[(i >> 6) * LDA + (i & 63)] = g_W1h[i];
    if (tid < D) sBias[tid] = b[tid];

    aggregate_phase((const uint4*)g_xh, base, tid, sA);
    __syncthreads();

    wmma_gemm(sA, sB, sC, tid);
    __syncthreads();

    // epilogue: bias + lrelu + *oisq -> fp16 global; 8 cols (1 uint4)/thread
    int g = tid >> 3, q = tid & 7;
    int on = base + g;
    if (on < N_NODES) {
        float sc = __ldg(&g_oisq[on]);
        half2 hv[4];
#pragma unroll
        for (int j = 0; j < 4; j++) {
            int c0 = q * 8 + 2 * j;
            float y0 = sC[g * LDC + c0]     + sBias[c0];
            float y1 = sC[g * LDC + c0 + 1] + sBias[c0 + 1];
            y0 = (y0 > 0.f) ? y0 : NEG_SLOPE * y0;
            y1 = (y1 > 0.f) ? y1 : NEG_SLOPE * y1;
            hv[j] = __floats2half2_rn(y0 * sc, y1 * sc);
        }
        ((uint4*)&g_h1h[(size_t)on * 32])[q] = *(uint4*)hv;
    }
}

// Layer 2 + classifier
__global__ void __launch_bounds__(512, 3) k_layer2(
    const float* __restrict__ b2,
    const float* __restrict__ Wc, const float* __restrict__ bc,
    float* __restrict__ out)
{
    __shared__ __align__(16) half  sA[64 * LDA];
    __shared__ __align__(16) half  sB[64 * LDA];
    __shared__ __align__(16) float sC[64 * LDC];
    __shared__ float sBias[D];
    __shared__ float sWc[D * 2];
    int tid = threadIdx.x;
    int base = blockIdx.x * 64;

    for (int i = tid; i < D * D; i += 512)
        sB[(i >> 6) * LDA + (i & 63)] = g_W2h[i];
    if (tid < D) sBias[tid] = b2[tid];
    if (tid >= 64 && tid < 64 + D * 2) sWc[tid - 64] = Wc[tid - 64];

    aggregate_phase((const uint4*)g_h1h, base, tid, sA);
    __syncthreads();

    wmma_gemm(sA, sB, sC, tid);
    __syncthreads();

    // epilogue: bias + lrelu, in-place in sC (same thread reads/writes)
    int g = tid >> 3, q = tid & 7;
#pragma unroll
    for (int j = 0; j < 8; j++) {
        int c0 = q * 8 + j;
        float y = sC[g * LDC + c0] + sBias[c0];
        y = (y > 0.f) ? y : NEG_SLOPE * y;
        sC[g * LDC + c0] = y;
    }
    __syncthreads();

    // classifier: out[n][c] = bc[c] + sum_k h2[n][k] * Wc[k][c]
    if (tid < 128) {
        int n = tid >> 1, c = tid & 1;
        int on = base + n;
        if (on < N_NODES) {
            float s = bc[c];
#pragma unroll
            for (int k = 0; k < D; k++) s += sC[n * LDC + k] * sWc[k * 2 + c];
            out[(size_t)on * 2 + c] = s;
        }
    }
}

// ---------------- launch ----------------
extern "C" void kernel_launch(void* const* d_in, const int* in_sizes, int n_in,
                              void* d_out, int out_size) {
    const float* x   = (const float*)d_in[0];
    const int*   src = (const int*)  d_in[1];
    const int*   dst = (const int*)  d_in[2];
    const float* W1  = (const float*)d_in[3];
    const float* b1  = (const float*)d_in[4];
    const float* W2  = (const float*)d_in[5];
    const float* b2  = (const float*)d_in[6];
    const float* Wc  = (const float*)d_in[7];
    const float* bc  = (const float*)d_in[8];
    float* out = (float*)d_out;

    k_deg     <<<(N_EDGES + 255) / 256, 256>>>(src, dst);
    k_alloc   <<<(N_NODES + 255) / 256, 256>>>();
    k_convfill<<<(N_NODES * (D / 4) + 255) / 256, 256>>>(x, W1, W2, src, dst);

    k_layer1<<<(N_NODES + 63) / 64, 512>>>(b1);
    k_layer2<<<(N_NODES + 63) / 64, 512>>>(b2, Wc, bc, out);
}

// round 16
// speedup vs baseline: 1.3351x; 1.0484x over previous
#include <cuda_runtime.h>
#include <cuda_fp16.h>
#include <mma.h>
#include <cstdint>

using namespace nvcuda;

#define N_NODES 100000
#define N_EDGES 1000000
#define D 64
#define NEG_SLOPE 0.01f

#define LDA 72   // half leading dim for A/B tiles
#define LDC 68   // float leading dim for C tile
#define ESRC_CAP (N_EDGES + 3 * N_NODES + 64)   // padded CSR capacity

// ---------------- scratch (no allocations allowed) ----------------
__device__ int   g_degOi[N_NODES];
__device__ int   g_degIi[N_NODES];
__device__ float g_oisq [N_NODES];
__device__ float g_iisq [N_NODES];
__device__ int   g_rowptr[N_NODES];       // padded CSR row start
__device__ int2  g_rows [N_NODES];        // {padded start, n4 = ceil(deg/4)}
__device__ int   g_rankE[N_EDGES];        // intra-node rank of each edge
__device__ int   g_total;                 // global row-offset cursor
__device__ __align__(16) int g_esrc[ESRC_CAP];   // CSR column (src), padded rows
__device__ __align__(16) half2 g_xh [((size_t)N_NODES + 1) * 32]; // x*oisq (+zero row)
__device__ __align__(16) half2 g_h1h[((size_t)N_NODES + 1) * 32]; // h1*oisq (+zero row)
__device__ __align__(16) half  g_W1h[D * D];
__device__ __align__(16) half  g_W2h[D * D];

// ------- degree histogram + rank capture (1 edge/thread) --------------------
// counters zero on entry: BSS-zero first call, re-zeroed by k_alloc after.
__global__ void k_deg(const int* __restrict__ src, const int* __restrict__ dst) {
    int e = blockIdx.x * blockDim.x + threadIdx.x;
    if (e >= N_EDGES) return;
    atomicAdd(&g_degOi[src[e]], 1);                    // no-return -> RED
    g_rankE[e] = atomicAdd(&g_degIi[dst[e]], 1);       // rank within dst row
}

// ------- padded row allocation + norms + pad fill; zero counters ------------
__global__ void k_alloc() {
    int i = blockIdx.x * blockDim.x + threadIdx.x;
    if (i >= N_NODES) return;
    int di = g_degIi[i];
    int dO = g_degOi[i];
    int padded = (di + 3) & ~3;
    int row = atomicAdd(&g_total, padded);   // grouping only; order irrelevant
    g_rowptr[i] = row;
    g_rows[i] = make_int2(row, padded >> 2);
    g_oisq[i] = rsqrtf((float)max(dO, 1));
    g_iisq[i] = rsqrtf((float)max(di, 1));
    for (int p = di; p < padded; p++) g_esrc[row + p] = N_NODES;  // dummy zero row
    g_degOi[i] = 0;                          // reset for next replay
    g_degIi[i] = 0;
}

// -- fused: CSR fill (no atomics) + x->fp16 convert + W->fp16; reset total ----
__global__ void k_convfill(const float* __restrict__ x,
                           const float* __restrict__ W1,
                           const float* __restrict__ W2,
                           const int* __restrict__ src,
                           const int* __restrict__ dst) {
    int t = blockIdx.x * blockDim.x + threadIdx.x;
    if (t == 0) g_total = 0;
    if (t < D * D)          g_W1h[t] = __float2half(W1[t]);
    else if (t < 2 * D * D) g_W2h[t - D * D] = __float2half(W2[t - D * D]);

    if (t < N_EDGES) {                       // CSR fill: rank precomputed
        int pos = __ldg(&g_rowptr[dst[t]]) + g_rankE[t];
        pos = min(pos, ESRC_CAP - 1);        // provable no-op; OOB guard
        g_esrc[pos] = src[t];
    }
    if (t < N_NODES * (D / 4)) {             // convert 1 float4 -> 2 half2
        int node = t >> 4;                   // 16 float4 per row
        float sc = g_oisq[node];
        float4 v = __ldg((const float4*)x + t);
        g_xh[t * 2 + 0] = __floats2half2_rn(v.x * sc, v.y * sc);
        g_xh[t * 2 + 1] = __floats2half2_rn(v.z * sc, v.w * sc);
    }
}

// =====================================================================
// Fused layers: fp16 gather (8 lanes/node, 4 nodes/warp), padded rows,
// pairwise HADD2 tree -> fp32 acc -> half smem -> wmma (16 warps)
// Block: 512 threads, 64 nodes.
// =====================================================================

// acc += float(a + b) elementwise; one fp16 rounding on the pair sum
__device__ __forceinline__ void hadd2_acc(uint4 a, uint4 b, float2 acc[4]) {
    const half2* ha = (const half2*)&a;
    const half2* hb = (const half2*)&b;
#pragma unroll
    for (int j = 0; j < 4; j++) {
        float2 f = __half22float2(__hadd2(ha[j], hb[j]));
        acc[j].x += f.x; acc[j].y += f.y;
    }
}

// lane l (0..7) of a node-group covers feats [8l, 8l+8) = one uint4
__device__ __forceinline__ void group_aggregate(const uint4* __restrict__ feat,
                                                int node, int l,
                                                float2 acc[4]) {
    int2 rd = g_rows[node];
    int start = rd.x, n4 = rd.y;
    if (n4 == 0) return;
    const int4* ip = (const int4*)(g_esrc + start);   // 16B-aligned (padded rows)
    int4 idx = __ldg(ip);
    for (int k = 1; ; k++) {
        int4 cur = idx;
        if (k < n4) idx = __ldg(ip + k);              // prefetch next 4 indices
        uint4 v0 = __ldg(feat + (size_t)cur.x * 8 + l);
        uint4 v1 = __ldg(feat + (size_t)cur.y * 8 + l);
        uint4 v2 = __ldg(feat + (size_t)cur.z * 8 + l);
        uint4 v3 = __ldg(feat + (size_t)cur.w * 8 + l);
        hadd2_acc(v0, v1, acc);                       // pairwise fp16 tree
        hadd2_acc(v2, v3, acc);
        if (k >= n4) break;
    }
}

// aggregate block's 64 nodes -> half tile sA[64][LDA] (scaled by iisq)
__device__ __forceinline__ void aggregate_phase(const uint4* __restrict__ feat,
                                                int base, int tid, half* sA) {
    int g = tid >> 3, l = tid & 7;          // 64 groups x 8 lanes
    int gn = base + g;
    float2 acc[4] = {{0,0},{0,0},{0,0},{0,0}};
    if (gn < N_NODES) {
        group_aggregate(feat, gn, l, acc);
        float fi = g_iisq[gn];
#pragma unroll
        for (int j = 0; j < 4; j++) { acc[j].x *= fi; acc[j].y *= fi; }
    }
    half2 h[4];
#pragma unroll
    for (int j = 0; j < 4; j++) h[j] = __floats2half2_rn(acc[j].x, acc[j].y);
    *(uint4*)&sA[g * LDA + 8 * l] = *(uint4*)h;
}

// 16 warps, one 16x16 tile each: sC = sA @ sB
__device__ __forceinline__ void wmma_gemm(const half* sA, const half* sB,
                                          float* sC, int tid) {
    int w = tid >> 5;                        // 0..15
    int mi = w >> 2, ni = w & 3;
    wmma::fragment<wmma::accumulator, 16, 16, 16, float> c;
    wmma::fill_fragment(c, 0.f);
#pragma unroll
    for (int kk = 0; kk < 4; kk++) {
        wmma::fragment<wmma::matrix_a, 16, 16, 16, half, wmma::row_major> a;
        wmma::fragment<wmma::matrix_b, 16, 16, 16, half, wmma::row_major> bf;
        wmma::load_matrix_sync(a, sA + mi * 16 * LDA + kk * 16, LDA);
        wmma::load_matrix_sync(bf, sB + kk * 16 * LDA + ni * 16, LDA);
        wmma::mma_sync(c, a, bf, c);
    }
    wmma::store_matrix_sync(sC + mi * 16 * LDC + ni * 16, c, LDC,
                            wmma::mem_row_major);
}

// Layer 1
__global__ void __launch_bounds__(512, 3) k_layer1(const float* __restrict__ b) {
    __shared__ __align__(16) half  sA[64 * LDA];
    __shared__ __align__(16) half  sB[64 * LDA];
    __shared__ __align__(16) float sC[64 * LDC];
    __shared__ float sBias[D];
    int tid = threadIdx.x;
    int base = blockIdx.x * 64;

    for (int i = tid; i < D * D; i += 512)
        sB[(i >> 6) * LDA + (i & 63)] = g_W1h[i];
    if (tid < D) sBias[tid] = b[tid];

    aggregate_phase((const uint4*)g_xh, base, tid, sA);
    __syncthreads();

    wmma_gemm(sA, sB, sC, tid);
    __syncthreads();

    // epilogue: bias + lrelu + *oisq -> fp16 global; 8 cols (1 uint4)/thread
    int g = tid >> 3, q = tid & 7;
    int on = base + g;
    if (on < N_NODES) {
        float sc = __ldg(&g_oisq[on]);
        half2 hv[4];
#pragma unroll
        for (int j = 0; j < 4; j++) {
            int c0 = q * 8 + 2 * j;
            float y0 = sC[g * LDC + c0]     + sBias[c0];
            float y1 = sC[g * LDC + c0 + 1] + sBias[c0 + 1];
            y0 = (y0 > 0.f) ? y0 : NEG_SLOPE * y0;
            y1 = (y1 > 0.f) ? y1 : NEG_SLOPE * y1;
            hv[j] = __floats2half2_rn(y0 * sc, y1 * sc);
        }
        ((uint4*)&g_h1h[(size_t)on * 32])[q] = *(uint4*)hv;
    }
}

// Layer 2 + classifier
__global__ void __launch_bounds__(512, 3) k_layer2(
    const float* __restrict__ b2,
    const float* __restrict__ Wc, const float* __restrict__ bc,
    float* __restrict__ out)
{
    __shared__ __align__(16) half  sA[64 * LDA];
    __shared__ __align__(16) half  sB[64 * LDA];
    __shared__ __align__(16) float sC[64 * LDC];
    __shared__ float sBias[D];
    __shared__ float sWc[D * 2];
    int tid = threadIdx.x;
    int base = blockIdx.x * 64;

    for (int i = tid; i < D * D; i += 512)
        sB[(i >> 6) * LDA + (i & 63)] = g_W2h[i];
    if (tid < D) sBias[tid] = b2[tid];
    if (tid >= 64 && tid < 64 + D * 2) sWc[tid - 64] = Wc[tid - 64];

    aggregate_phase((const uint4*)g_h1h, base, tid, sA);
    __syncthreads();

    wmma_gemm(sA, sB, sC, tid);
    __syncthreads();

    // epilogue: bias + lrelu, in-place in sC (same thread reads/writes)
    int g = tid >> 3, q = tid & 7;
#pragma unroll
    for (int j = 0; j < 8; j++) {
        int c0 = q * 8 + j;
        float y = sC[g * LDC + c0] + sBias[c0];
        y = (y > 0.f) ? y : NEG_SLOPE * y;
        sC[g * LDC + c0] = y;
    }
    __syncthreads();

    // classifier: out[n][c] = bc[c] + sum_k h2[n][k] * Wc[k][c]
    if (tid < 128) {
        int n = tid >> 1, c = tid & 1;
        int on = base + n;
        if (on < N_NODES) {
            float s = bc[c];
#pragma unroll
            for (int k = 0; k < D; k++) s += sC[n * LDC + k] * sWc[k * 2 + c];
            out[(size_t)on * 2 + c] = s;
        }
    }
}

// ---------------- launch ----------------
extern "C" void kernel_launch(void* const* d_in, const int* in_sizes, int n_in,
                              void* d_out, int out_size) {
    const float* x   = (const float*)d_in[0];
    const int*   src = (const int*)  d_in[1];
    const int*   dst = (const int*)  d_in[2];
    const float* W1  = (const float*)d_in[3];
    const float* b1  = (const float*)d_in[4];
    const float* W2  = (const float*)d_in[5];
    const float* b2  = (const float*)d_in[6];
    const float* Wc  = (const float*)d_in[7];
    const float* bc  = (const float*)d_in[8];
    float* out = (float*)d_out;

    k_deg     <<<(N_EDGES + 255) / 256, 256>>>(src, dst);
    k_alloc   <<<(N_NODES + 255) / 256, 256>>>();
    k_convfill<<<(N_NODES * (D / 4) + 255) / 256, 256>>>(x, W1, W2, src, dst);

    k_layer1<<<(N_NODES + 63) / 64, 512>>>(b1);
    k_layer2<<<(N_NODES + 63) / 64, 512>>>(b2, Wc, bc, out);
}